// round 9
// baseline (speedup 1.0000x reference)
#include <cuda_runtime.h>
#include <stdint.h>

// Problem constants
#define BSZ  16
#define SEQN 1024
#define NVV  512
#define DMM  256
#define KCL  8

// Tiling: tile = (b, vchunk) -> 128 tiles; each tile split into 8 k-slices.
#define KB 16                  // s per inner chunk
#define VT 64                  // v-rows per tile
#define SPLIT 8                // k-slices per tile
#define KS (SEQN / SPLIT)      // 128 s per block
#define NCH (KS / KB)          // 8 chunks per block
#define NTILE 128              // 16 b x 8 vchunks

// -------- device scratch ---------------------------------------------------
__device__ float g_py[(size_t)NTILE * SPLIT * VT * DMM];  // 64 MB partials
__device__ float g_soft[BSZ * NVV * KCL];
__device__ int   g_f1[NTILE * SPLIT];
__device__ int   g_f2[NTILE * SPLIT];

typedef unsigned long long ull;

// -------- packed f32x2 helpers --------------------------------------------
__device__ __forceinline__ ull pack2(float x, float y) {
    ull r; asm("mov.b64 %0, {%1, %2};" : "=l"(r) : "f"(x), "f"(y)); return r;
}
__device__ __forceinline__ float2 unpk2(ull a) {
    float2 f; asm("mov.b64 {%0, %1}, %2;" : "=f"(f.x), "=f"(f.y) : "l"(a)); return f;
}
__device__ __forceinline__ void fma2(ull& d, ull a, ull b) {
    asm("fma.rn.f32x2 %0, %1, %2, %0;" : "+l"(d) : "l"(a), "l"(b));
}

// -------- JAX threefry2x32 (key = (0,7)), partitionable 32-bit fold -------
__device__ __forceinline__ uint32_t rotl32(uint32_t x, int r) {
    return (x << r) | (x >> (32 - r));
}
__device__ __forceinline__ uint32_t threefry_bits32(uint32_t c0, uint32_t c1) {
    const uint32_t ks0 = 0u, ks1 = 7u;
    const uint32_t ks2 = ks0 ^ ks1 ^ 0x1BD11BDAu;
    uint32_t x0 = c0 + ks0, x1 = c1 + ks1;
#define TFR(r) { x0 += x1; x1 = rotl32(x1, (r)); x1 ^= x0; }
    TFR(13) TFR(15) TFR(26) TFR(6)   x0 += ks1; x1 += ks2 + 1u;
    TFR(17) TFR(29) TFR(16) TFR(24)  x0 += ks2; x1 += ks0 + 2u;
    TFR(13) TFR(15) TFR(26) TFR(6)   x0 += ks0; x1 += ks1 + 3u;
    TFR(17) TFR(29) TFR(16) TFR(24)  x0 += ks1; x1 += ks2 + 4u;
    TFR(13) TFR(15) TFR(26) TFR(6)   x0 += ks2; x1 += ks0 + 5u;
#undef TFR
    return x0 ^ x1;
}

// -------- kernel 0: zero sync flags (must precede mega kernel each run) ---
__global__ void zero_flags_kernel() {
    int i = blockIdx.x * 1024 + threadIdx.x;
    if (i < NTILE * SPLIT) { g_f1[i] = 0; g_f2[i] = 0; }
}

// -------- mega kernel: partial GEMM + sibling-sync combine + output write -
// Block bid: tile = bid>>3 (b = tile>>3, vchunk = tile&7), j = bid&7 (k-slice
// AND v-slice-for-combine AND k-row-for-output).
__global__ __launch_bounds__(256, 2)
void mega_kernel(const float* __restrict__ x, const float* __restrict__ W,
                 const float* __restrict__ bias, const float* __restrict__ ce,
                 float4* __restrict__ out) {
    __shared__ __align__(16) float As[2][KB][VT];     // 8 KB
    __shared__ __align__(16) float Bs[2][KB][DMM];    // 32 KB

    const int bid  = blockIdx.x;
    const int tile = bid >> 3;
    const int j    = bid & 7;
    const int b    = tile >> 3;
    const int v0   = (tile & 7) * VT;
    const int sbeg = j * KS;

    const int tid  = threadIdx.x;
    const int w    = tid >> 5;
    const int lane = tid & 31;
    const int vpanel = w & 1;             // 0..1
    const int dpanel = w >> 1;            // 0..3
    const int vl = lane & 3;              // 0..3
    const int dl = lane >> 2;             // 0..7
    const int vbase = vpanel * 32 + vl * 8;
    const int dbase = dpanel * 64 + dl * 8;

    const float* xb = x + (size_t)b * SEQN * NVV;
    const int xk = tid >> 4, xv = tid & 15;

    ull c2[8][4];
#pragma unroll
    for (int i = 0; i < 8; ++i)
#pragma unroll
        for (int q = 0; q < 4; ++q) c2[i][q] = 0ull;

    // ---- mainloop over 8 chunks of this k-slice ----
    float4 xa = *(const float4*)(xb + (size_t)(sbeg + xk) * NVV + v0 + xv * 4);
    float4 wa0 = *(const float4*)(W + (size_t)tid * SEQN + sbeg + 0);
    float4 wa1 = *(const float4*)(W + (size_t)tid * SEQN + sbeg + 4);
    float4 wa2 = *(const float4*)(W + (size_t)tid * SEQN + sbeg + 8);
    float4 wa3 = *(const float4*)(W + (size_t)tid * SEQN + sbeg + 12);

    *(float4*)&As[0][xk][xv * 4] = xa;
    Bs[0][0][tid]  = wa0.x; Bs[0][1][tid]  = wa0.y;
    Bs[0][2][tid]  = wa0.z; Bs[0][3][tid]  = wa0.w;
    Bs[0][4][tid]  = wa1.x; Bs[0][5][tid]  = wa1.y;
    Bs[0][6][tid]  = wa1.z; Bs[0][7][tid]  = wa1.w;
    Bs[0][8][tid]  = wa2.x; Bs[0][9][tid]  = wa2.y;
    Bs[0][10][tid] = wa2.z; Bs[0][11][tid] = wa2.w;
    Bs[0][12][tid] = wa3.x; Bs[0][13][tid] = wa3.y;
    Bs[0][14][tid] = wa3.z; Bs[0][15][tid] = wa3.w;
    __syncthreads();

    for (int c = 0; c < NCH; ++c) {
        const int cur = c & 1;
        const int nxt = cur ^ 1;
        if (c + 1 < NCH) {
            int sn = sbeg + (c + 1) * KB;
            xa  = *(const float4*)(xb + (size_t)(sn + xk) * NVV + v0 + xv * 4);
            wa0 = *(const float4*)(W + (size_t)tid * SEQN + sn + 0);
            wa1 = *(const float4*)(W + (size_t)tid * SEQN + sn + 4);
            wa2 = *(const float4*)(W + (size_t)tid * SEQN + sn + 8);
            wa3 = *(const float4*)(W + (size_t)tid * SEQN + sn + 12);
        }

#pragma unroll
        for (int k = 0; k < KB; ++k) {
            float4 a0 = *(const float4*)&As[cur][k][vbase];
            float4 a1 = *(const float4*)&As[cur][k][vbase + 4];
            ulonglong2 b01 = *(const ulonglong2*)&Bs[cur][k][dbase];
            ulonglong2 b23 = *(const ulonglong2*)&Bs[cur][k][dbase + 4];
            float av[8] = {a0.x, a0.y, a0.z, a0.w, a1.x, a1.y, a1.z, a1.w};
#pragma unroll
            for (int i = 0; i < 8; ++i) {
                ull a = pack2(av[i], av[i]);
                fma2(c2[i][0], a, b01.x);
                fma2(c2[i][1], a, b01.y);
                fma2(c2[i][2], a, b23.x);
                fma2(c2[i][3], a, b23.y);
            }
        }

        if (c + 1 < NCH) {
            *(float4*)&As[nxt][xk][xv * 4] = xa;
            Bs[nxt][0][tid]  = wa0.x; Bs[nxt][1][tid]  = wa0.y;
            Bs[nxt][2][tid]  = wa0.z; Bs[nxt][3][tid]  = wa0.w;
            Bs[nxt][4][tid]  = wa1.x; Bs[nxt][5][tid]  = wa1.y;
            Bs[nxt][6][tid]  = wa1.z; Bs[nxt][7][tid]  = wa1.w;
            Bs[nxt][8][tid]  = wa2.x; Bs[nxt][9][tid]  = wa2.y;
            Bs[nxt][10][tid] = wa2.z; Bs[nxt][11][tid] = wa2.w;
            Bs[nxt][12][tid] = wa3.x; Bs[nxt][13][tid] = wa3.y;
            Bs[nxt][14][tid] = wa3.z; Bs[nxt][15][tid] = wa3.w;
            __syncthreads();
        }
    }

    // ---- store partials to g_py[tile][j][v][d] ----
    float* pt = g_py + ((size_t)(tile * SPLIT + j) * VT) * DMM;
#pragma unroll
    for (int i = 0; i < 8; ++i) {
        float2 p0 = unpk2(c2[i][0]);
        float2 p1 = unpk2(c2[i][1]);
        float2 p2 = unpk2(c2[i][2]);
        float2 p3 = unpk2(c2[i][3]);
        float4 lo = make_float4(p0.x, p0.y, p1.x, p1.y);
        float4 hi = make_float4(p2.x, p2.y, p3.x, p3.y);
        *(float4*)&pt[(size_t)(vbase + i) * DMM + dbase]     = lo;
        *(float4*)&pt[(size_t)(vbase + i) * DMM + dbase + 4] = hi;
    }
    __syncthreads();
    if (tid == 0) {
        __threadfence();
        *((volatile int*)&g_f1[bid]) = 1;
    }

    // ---- normalize cluster_emb + stage bias (overlaps sibling wait) ----
    __syncthreads();                       // mainloop smem reads done
    float* cn_s   = &As[0][0][0];          // 8 x 256 floats = 8 KB (exact)
    float* bias_s = &Bs[0][0][0];          // 256 floats
    float* vals   = bias_s + DMM;          // 64 floats (phase B)
    {
        const float* row = ce + w * DMM;
        float s = 0.f;
#pragma unroll
        for (int q = 0; q < DMM / 32; ++q) {
            float t = row[lane + q * 32];
            s += t * t;
        }
#pragma unroll
        for (int o = 16; o; o >>= 1) s += __shfl_xor_sync(0xffffffffu, s, o);
        float nrm = fmaxf(sqrtf(s), 1e-12f);
#pragma unroll
        for (int q = 0; q < DMM / 32; ++q)
            cn_s[w * DMM + lane + q * 32] = row[lane + q * 32] / nrm;
    }
    bias_s[tid] = bias[tid];

    // ---- wait for all 8 siblings' partials ----
    if (tid < SPLIT) {
        volatile int* f = (volatile int*)&g_f1[tile * SPLIT + tid];
        while (*f == 0) { __nanosleep(128); }
    }
    __syncthreads();
    __threadfence();

    // ---- phase A: combine v-slice j (8 v), sinkhorn, publish soft ----
    {
        int vloc = j * 8 + (tid >> 5);     // this warp's v within tile
        int dseg = lane * 8;
        const float* pyt = g_py + ((size_t)tile * SPLIT * VT + vloc) * DMM + dseg;
        float y[8];
#pragma unroll
        for (int q = 0; q < 8; ++q) y[q] = 0.f;
#pragma unroll
        for (int jj = 0; jj < SPLIT; ++jj) {
            const float4* p4 = (const float4*)(pyt + (size_t)jj * VT * DMM);
            float4 lo = p4[0], hi = p4[1];
            y[0] += lo.x; y[1] += lo.y; y[2] += lo.z; y[3] += lo.w;
            y[4] += hi.x; y[5] += hi.y; y[6] += hi.z; y[7] += hi.w;
        }
#pragma unroll
        for (int q = 0; q < 8; ++q) y[q] += bias_s[dseg + q];

        float r[9];
        r[0] = 0.f;
#pragma unroll
        for (int q = 0; q < 8; ++q) r[0] += y[q] * y[q];
#pragma unroll
        for (int kk = 0; kk < KCL; ++kk) {
            const float* cp = &cn_s[kk * DMM + dseg];
            float s = 0.f;
#pragma unroll
            for (int q = 0; q < 8; ++q) s += y[q] * cp[q];
            r[1 + kk] = s;
        }
#pragma unroll
        for (int o = 16; o; o >>= 1) {
#pragma unroll
            for (int q = 0; q < 9; ++q)
                r[q] += __shfl_xor_sync(0xffffffffu, r[q], o);
        }
        if (lane == 0) {
            float nrm = fmaxf(sqrtf(r[0]), 1e-12f);
            float e[KCL], esum = 0.f;
#pragma unroll
            for (int kk = 0; kk < KCL; ++kk) {
                float prob = r[1 + kk] / nrm;
                e[kk] = expf(prob / 0.05f);
                esum += e[kk];
            }
            float* dst = g_soft + ((size_t)(b * NVV + v0 + vloc)) * KCL;
#pragma unroll
            for (int kk = 0; kk < KCL; ++kk) dst[kk] = e[kk] / esum;
        }
    }
    __syncthreads();
    if (tid == 0) {
        __threadfence();
        *((volatile int*)&g_f2[bid]) = 1;
    }

    // ---- wait for full tile's soft ----
    if (tid < SPLIT) {
        volatile int* f = (volatile int*)&g_f2[tile * SPLIT + tid];
        while (*f == 0) { __nanosleep(128); }
    }
    __syncthreads();
    __threadfence();

    // ---- phase B: bernoulli + write output k-slice j (64 contiguous rows) -
    if (tid < VT) {
        int r = j * (BSZ * NVV) + b * NVV + v0 + tid;   // output row (k,b,v)
        float soft = g_soft[((size_t)(b * NVV + v0 + tid)) * KCL + j];
        uint32_t bits = threefry_bits32(0u, (uint32_t)r);
        float f = __uint_as_float((bits >> 9) | 0x3f800000u) - 1.0f;
        float u = fmaxf(0.0f, f);
        vals[tid] = (u < soft) ? 1.0f : 0.0f;
    }
    __syncthreads();

    {
        size_t row0 = (size_t)j * (BSZ * NVV) + b * NVV + v0;
        float4* o = out + row0 * 256 + tid;
#pragma unroll
        for (int i = 0; i < VT; ++i) {
            float v = vals[i];
            __stcs(&o[(size_t)i * 256], make_float4(v, v, v, v));
        }
    }
}

// -------- launch -----------------------------------------------------------
extern "C" void kernel_launch(void* const* d_in, const int* in_sizes, int n_in,
                              void* d_out, int out_size) {
    const float* x = nullptr;
    const float* W = nullptr;
    const float* bias = nullptr;
    const float* ce = nullptr;
    for (int i = 0; i < n_in; ++i) {
        switch (in_sizes[i]) {
            case BSZ * SEQN * NVV: x    = (const float*)d_in[i]; break;
            case DMM * SEQN:       W    = (const float*)d_in[i]; break;
            case DMM:              bias = (const float*)d_in[i]; break;
            case KCL * DMM:        ce   = (const float*)d_in[i]; break;
            default: break;
        }
    }
    float4* out = (float4*)d_out;

    zero_flags_kernel<<<1, 1024>>>();
    mega_kernel<<<NTILE * SPLIT, 256>>>(x, W, bias, ce, out);
    (void)out_size;
}